// round 5
// baseline (speedup 1.0000x reference)
#include <cuda_runtime.h>
#include <cstdint>

// ---------------------------------------------------------------------------
// Modified MHA (no input proj) + dual output projections.
//   B=16, L=S=1024, E=512, H=8, hd=64. fp32 in/out, TF32 tensor-core math.
// Round 5: fragment-native shared layouts (LDS.128 A-frags, LDS.64 B-frags),
//          warp m-tile 32, block m-tile 128, Q fragments register-resident.
// ---------------------------------------------------------------------------

#define BB 16
#define LL 1024
#define SS 1024
#define EE 512
#define HH 8
#define HD 64

// 33.5 MB scratch for attention output
__device__ float g_attn[(size_t)BB * LL * EE];

// ---- helpers --------------------------------------------------------------

__device__ __forceinline__ uint32_t f2tf32(float x) {
    uint32_t r;
    asm volatile("cvt.rna.tf32.f32 %0, %1;" : "=r"(r) : "f"(x));
    return r;
}

// mma.sync m16n8k8 tf32: A row-major 16x8, B col-major 8x8, C/D fp32 16x8.
// lane = g*4+t (g=lane>>2, t=lane&3):
//   a0=A[g][t] a1=A[g+8][t] a2=A[g][t+4] a3=A[g+8][t+4]
//   b0=B[k=t][n=g] b1=B[k=t+4][n=g]
//   c0=C[g][2t] c1=C[g][2t+1] c2=C[g+8][2t] c3=C[g+8][2t+1]
__device__ __forceinline__ void mma_tf32(float c[4], const uint32_t a[4],
                                         uint32_t b0, uint32_t b1) {
    asm volatile(
        "mma.sync.aligned.m16n8k8.row.col.f32.tf32.tf32.f32 "
        "{%0,%1,%2,%3}, {%4,%5,%6,%7}, {%8,%9}, {%0,%1,%2,%3};\n"
        : "+f"(c[0]), "+f"(c[1]), "+f"(c[2]), "+f"(c[3])
        : "r"(a[0]), "r"(a[1]), "r"(a[2]), "r"(a[3]), "r"(b0), "r"(b1));
}

// ---- fragment-layout shared memory ----------------------------------------
// A-frag region: 16x8 fragments stored so lane d's 4 regs are contiguous.
//   element (r,c) of a frag: slot d = (r&7)*4 + (c&3), reg = 2*((c>>2)&1) + (r>>3)
//   float offset = f*AF_STRIDE + ((d*4 + reg) ^ swz(d)),  swz(d)=((d>>2)&6)<<1
// Stride 132 (not 128) decorrelates frag bases across banks; the XOR swizzle
// spreads the P-epilogue paired stores. LDS.128 at (lane*4)^swz stays 16B-aligned
// and conflict-free.
#define AF_STRIDE 132
__device__ __forceinline__ int af_off(int f, int d, int reg) {
    return f * AF_STRIDE + (((d * 4 + reg)) ^ (((d >> 2) & 6) << 1));
}

// B-frag region: 8(k)x8(n) fragments, lane d = n*4 + (k&3), reg = k>>2.
//   float offset = f*BF_STRIDE + d*2 + reg   (LDS.64 per lane, conflict-free)
#define BF_STRIDE 66

// ---- Kernel 1: flash attention ---------------------------------------------
// Block = 128 threads (4 warps), 128 query rows; warp owns 32 rows (mi=0,1).
// S streamed in 64-row tiles. Q fragments register-resident.

#define QROWS 128
#define STILE 64
#define SP_FLOATS (64 * AF_STRIDE)   // 8448: 8(mi) x 8(ki) A-frags (Q stage / P)
#define SB_FLOATS (64 * BF_STRIDE)   // 4224: 8x8 B-frags
#define ATTN_SMEM ((SP_FLOATS + 2 * SB_FLOATS) * 4)

__global__ void __launch_bounds__(128, 2)
attn_kernel(const float* __restrict__ q,
            const float* __restrict__ kmat,
            const float* __restrict__ vmat)
{
    extern __shared__ float sm1[];
    float* sP = sm1;                 // A-frag region (Q staging, then P)
    float* sK = sP + SP_FLOATS;      // B-frag, frag f = ni*8 + ki
    float* sV = sK + SB_FLOATS;      // B-frag, frag f = ki*8 + ni

    const int tid  = threadIdx.x;
    const int warp = tid >> 5;
    const int lane = tid & 31;
    const int g = lane >> 2;
    const int t = lane & 3;

    const int ltile = blockIdx.x;  // 0..7
    const int h     = blockIdx.y;  // 0..7
    const int b     = blockIdx.z;  // 0..15

    // ---- stage Q (128x64) into A-frag layout, scaled + tf32 ----
    {
        const float* qbase = q + ((size_t)b * LL + (size_t)ltile * QROWS) * EE + h * HD;
        for (int i = tid; i < QROWS * 16; i += 128) {
            int row = i >> 4;
            int c4  = (i & 15) * 4;
            float4 val = *reinterpret_cast<const float4*>(qbase + (size_t)row * EE + c4);
            int mi = row >> 4, r = row & 15, ki = c4 >> 3;
            int reg = ((c4 >> 2) & 1) * 2 + (r >> 3);
            int dbase = (r & 7) * 4;
            float vv[4] = {val.x * 0.125f, val.y * 0.125f, val.z * 0.125f, val.w * 0.125f};
            #pragma unroll
            for (int j = 0; j < 4; j++)
                sP[af_off(mi * 8 + ki, dbase + j, reg)] = __uint_as_float(f2tf32(vv[j]));
        }
    }
    __syncthreads();

    // ---- Q fragments to registers (warp reads only its own region) ----
    uint32_t qf[2][8][4];
    #pragma unroll
    for (int mi = 0; mi < 2; mi++)
        #pragma unroll
        for (int ki = 0; ki < 8; ki++) {
            float4 v = *reinterpret_cast<const float4*>(
                sP + af_off((warp * 2 + mi) * 8 + ki, lane, 0));
            qf[mi][ki][0] = __float_as_uint(v.x);
            qf[mi][ki][1] = __float_as_uint(v.y);
            qf[mi][ki][2] = __float_as_uint(v.z);
            qf[mi][ki][3] = __float_as_uint(v.w);
        }
    // No block sync needed: each warp's P region == its own Q region.

    float m_prev[2][2] = {{-1e30f, -1e30f}, {-1e30f, -1e30f}};
    float l_sum[2][2]  = {{0.f, 0.f}, {0.f, 0.f}};
    float acc[2][8][4];
    #pragma unroll
    for (int mi = 0; mi < 2; mi++)
        #pragma unroll
        for (int ni = 0; ni < 8; ni++)
            #pragma unroll
            for (int i = 0; i < 4; i++) acc[mi][ni][i] = 0.f;

    const float* kb = kmat + (size_t)b * SS * EE + h * HD;
    const float* vb = vmat + (size_t)b * SS * EE + h * HD;

    for (int st = 0; st < SS; st += STILE) {
        __syncthreads();  // prior-iteration sK/sV reads complete

        // ---- stage K,V 64x64 tiles into B-frag layouts ----
        for (int i = tid; i < 64 * 16; i += 128) {
            int row = i >> 4;
            int c4  = (i & 15) * 4;
            float4 kv = *reinterpret_cast<const float4*>(kb + (size_t)(st + row) * EE + c4);
            {   // K: n = s-row, k = d-col. frag f = ni*8 + ki
                int ni = row >> 3, nn = row & 7, ki = c4 >> 3;
                int reg = (c4 >> 2) & 1;
                float vv[4] = {kv.x, kv.y, kv.z, kv.w};
                #pragma unroll
                for (int j = 0; j < 4; j++)
                    sK[(ni * 8 + ki) * BF_STRIDE + (nn * 4 + j) * 2 + reg] =
                        __uint_as_float(f2tf32(vv[j]));
            }
            float4 vv4 = *reinterpret_cast<const float4*>(vb + (size_t)(st + row) * EE + c4);
            {   // V: k = s-row, n = d-col. frag f = ki*8 + ni
                int ki = row >> 3, kk = row & 7, ni = c4 >> 3;
                int reg = kk >> 2;
                int nnb = c4 & 4;
                float vv[4] = {vv4.x, vv4.y, vv4.z, vv4.w};
                #pragma unroll
                for (int j = 0; j < 4; j++)
                    sV[(ki * 8 + ni) * BF_STRIDE + ((nnb + j) * 4 + (kk & 3)) * 2 + reg] =
                        __uint_as_float(f2tf32(vv[j]));
            }
        }
        __syncthreads();

        // ---- scores: sc[mi] = Q[mi] @ K^T (B frags loaded once, reused 2 mi) ----
        float sc[2][8][4];
        #pragma unroll
        for (int mi = 0; mi < 2; mi++)
            #pragma unroll
            for (int ni = 0; ni < 8; ni++)
                #pragma unroll
                for (int i = 0; i < 4; i++) sc[mi][ni][i] = 0.f;

        #pragma unroll
        for (int ki = 0; ki < 8; ki++) {
            #pragma unroll
            for (int ni = 0; ni < 8; ni++) {
                float2 bv = *reinterpret_cast<const float2*>(
                    sK + (ni * 8 + ki) * BF_STRIDE + lane * 2);
                uint32_t b0 = __float_as_uint(bv.x), b1 = __float_as_uint(bv.y);
                mma_tf32(sc[0][ni], qf[0][ki], b0, b1);
                mma_tf32(sc[1][ni], qf[1][ki], b0, b1);
            }
        }

        // ---- online softmax; write P directly in A-frag layout ----
        const int dbase = g * 4 + 2 * (t & 1);
        const int regb  = 2 * (t >> 1);
        #pragma unroll
        for (int mi = 0; mi < 2; mi++) {
            float mt0 = -1e30f, mt1 = -1e30f;
            #pragma unroll
            for (int ni = 0; ni < 8; ni++) {
                mt0 = fmaxf(mt0, fmaxf(sc[mi][ni][0], sc[mi][ni][1]));
                mt1 = fmaxf(mt1, fmaxf(sc[mi][ni][2], sc[mi][ni][3]));
            }
            #pragma unroll
            for (int o = 1; o <= 2; o <<= 1) {
                mt0 = fmaxf(mt0, __shfl_xor_sync(0xffffffffu, mt0, o));
                mt1 = fmaxf(mt1, __shfl_xor_sync(0xffffffffu, mt1, o));
            }
            float mn0 = fmaxf(m_prev[mi][0], mt0);
            float mn1 = fmaxf(m_prev[mi][1], mt1);
            float al0 = __expf(m_prev[mi][0] - mn0);
            float al1 = __expf(m_prev[mi][1] - mn1);
            m_prev[mi][0] = mn0; m_prev[mi][1] = mn1;

            float rs0 = 0.f, rs1 = 0.f;
            const int fb = (warp * 2 + mi) * 8;
            #pragma unroll
            for (int ni = 0; ni < 8; ni++) {
                float p00 = __expf(sc[mi][ni][0] - mn0);
                float p01 = __expf(sc[mi][ni][1] - mn0);
                float p10 = __expf(sc[mi][ni][2] - mn1);
                float p11 = __expf(sc[mi][ni][3] - mn1);
                rs0 += p00 + p01;
                rs1 += p10 + p11;
                // (p00,p10) -> regs (regb, regb+1) at slot dbase; (p01,p11) at dbase+1
                *reinterpret_cast<float2*>(sP + af_off(fb + ni, dbase, regb)) =
                    make_float2(__uint_as_float(f2tf32(p00)), __uint_as_float(f2tf32(p10)));
                *reinterpret_cast<float2*>(sP + af_off(fb + ni, dbase + 1, regb)) =
                    make_float2(__uint_as_float(f2tf32(p01)), __uint_as_float(f2tf32(p11)));
            }
            #pragma unroll
            for (int o = 1; o <= 2; o <<= 1) {
                rs0 += __shfl_xor_sync(0xffffffffu, rs0, o);
                rs1 += __shfl_xor_sync(0xffffffffu, rs1, o);
            }
            l_sum[mi][0] = l_sum[mi][0] * al0 + rs0;
            l_sum[mi][1] = l_sum[mi][1] * al1 + rs1;
            #pragma unroll
            for (int ni = 0; ni < 8; ni++) {
                acc[mi][ni][0] *= al0; acc[mi][ni][1] *= al0;
                acc[mi][ni][2] *= al1; acc[mi][ni][3] *= al1;
            }
        }
        __syncwarp();  // P stores visible to this warp's fragment loads

        // ---- acc += P @ V ----
        #pragma unroll
        for (int ki = 0; ki < 8; ki++) {
            uint32_t pa[2][4];
            #pragma unroll
            for (int mi = 0; mi < 2; mi++) {
                float4 v = *reinterpret_cast<const float4*>(
                    sP + af_off((warp * 2 + mi) * 8 + ki, lane, 0));
                pa[mi][0] = __float_as_uint(v.x);
                pa[mi][1] = __float_as_uint(v.y);
                pa[mi][2] = __float_as_uint(v.z);
                pa[mi][3] = __float_as_uint(v.w);
            }
            #pragma unroll
            for (int ni = 0; ni < 8; ni++) {
                float2 bv = *reinterpret_cast<const float2*>(
                    sV + (ki * 8 + ni) * BF_STRIDE + lane * 2);
                uint32_t b0 = __float_as_uint(bv.x), b1 = __float_as_uint(bv.y);
                mma_tf32(acc[0][ni], pa[0], b0, b1);
                mma_tf32(acc[1][ni], pa[1], b0, b1);
            }
        }
    }

    // ---- epilogue: normalize + write attn ----
    #pragma unroll
    for (int mi = 0; mi < 2; mi++) {
        float inv0 = 1.f / l_sum[mi][0];
        float inv1 = 1.f / l_sum[mi][1];
        float* ob = g_attn +
            ((size_t)b * LL + (size_t)ltile * QROWS + warp * 32 + mi * 16) * EE + h * HD;
        #pragma unroll
        for (int ni = 0; ni < 8; ni++) {
            int col = ni * 8 + 2 * t;
            *reinterpret_cast<float2*>(ob + (size_t)g * EE + col) =
                make_float2(acc[mi][ni][0] * inv0, acc[mi][ni][1] * inv0);
            *reinterpret_cast<float2*>(ob + (size_t)(g + 8) * EE + col) =
                make_float2(acc[mi][ni][2] * inv1, acc[mi][ni][3] * inv1);
        }
    }
}

// ---- Kernel 2: dual output projection --------------------------------------
// Block tile 128(m) x 64(n), warp m=32. Both W matrices resident.

#define PROJ_SMEM ((SP_FLOATS + 2 * SB_FLOATS) * 4)

__global__ void __launch_bounds__(128, 2)
proj_kernel(const float* __restrict__ w1, const float* __restrict__ bias1,
            const float* __restrict__ w2, const float* __restrict__ bias2,
            float* __restrict__ out)
{
    extern __shared__ float sm2[];
    float* sA  = sm2;                 // A-frag region: 8(mi) x 8(ki)
    float* sW1 = sA + SP_FLOATS;      // B-frag, f = ni*8 + ki
    float* sW2 = sW1 + SB_FLOATS;

    const int tid  = threadIdx.x;
    const int warp = tid >> 5;
    const int lane = tid & 31;
    const int g = lane >> 2;
    const int t = lane & 3;

    const int mt = blockIdx.x;   // 0..127
    const int nt = blockIdx.y;   // 0..7

    const float* ab  = g_attn + (size_t)mt * 128 * EE;
    const float* w1b = w1 + (size_t)nt * 64 * EE;
    const float* w2b = w2 + (size_t)nt * 64 * EE;

    float acc1[2][8][4], acc2[2][8][4];
    #pragma unroll
    for (int mi = 0; mi < 2; mi++)
        #pragma unroll
        for (int ni = 0; ni < 8; ni++)
            #pragma unroll
            for (int i = 0; i < 4; i++) { acc1[mi][ni][i] = 0.f; acc2[mi][ni][i] = 0.f; }

    for (int k0 = 0; k0 < EE; k0 += 64) {
        __syncthreads();

        // stage A (128 x 64) into A-frag layout
        for (int i = tid; i < 128 * 16; i += 128) {
            int row = i >> 4;
            int c4  = (i & 15) * 4;
            float4 av = *reinterpret_cast<const float4*>(ab + (size_t)row * EE + k0 + c4);
            int mi = row >> 4, r = row & 15, ki = c4 >> 3;
            int reg = ((c4 >> 2) & 1) * 2 + (r >> 3);
            int dbase = (r & 7) * 4;
            float vv[4] = {av.x, av.y, av.z, av.w};
            #pragma unroll
            for (int j = 0; j < 4; j++)
                sA[af_off(mi * 8 + ki, dbase + j, reg)] = __uint_as_float(f2tf32(vv[j]));
        }
        // stage W1, W2 (64 x 64) into B-frag layout
        for (int i = tid; i < 64 * 16; i += 128) {
            int row = i >> 4;
            int c4  = (i & 15) * 4;
            int ni = row >> 3, nn = row & 7, ki = c4 >> 3;
            int reg = (c4 >> 2) & 1;
            float4 wv = *reinterpret_cast<const float4*>(w1b + (size_t)row * EE + k0 + c4);
            float v1[4] = {wv.x, wv.y, wv.z, wv.w};
            float4 wv2 = *reinterpret_cast<const float4*>(w2b + (size_t)row * EE + k0 + c4);
            float v2[4] = {wv2.x, wv2.y, wv2.z, wv2.w};
            #pragma unroll
            for (int j = 0; j < 4; j++) {
                sW1[(ni * 8 + ki) * BF_STRIDE + (nn * 4 + j) * 2 + reg] =
                    __uint_as_float(f2tf32(v1[j]));
                sW2[(ni * 8 + ki) * BF_STRIDE + (nn * 4 + j) * 2 + reg] =
                    __uint_as_float(f2tf32(v2[j]));
            }
        }
        __syncthreads();

        #pragma unroll
        for (int ki = 0; ki < 8; ki++) {
            uint32_t af[2][4];
            #pragma unroll
            for (int mi = 0; mi < 2; mi++) {
                float4 v = *reinterpret_cast<const float4*>(
                    sA + af_off((warp * 2 + mi) * 8 + ki, lane, 0));
                af[mi][0] = __float_as_uint(v.x);
                af[mi][1] = __float_as_uint(v.y);
                af[mi][2] = __float_as_uint(v.z);
                af[mi][3] = __float_as_uint(v.w);
            }
            #pragma unroll
            for (int ni = 0; ni < 8; ni++) {
                float2 b1 = *reinterpret_cast<const float2*>(
                    sW1 + (ni * 8 + ki) * BF_STRIDE + lane * 2);
                uint32_t b10 = __float_as_uint(b1.x), b11 = __float_as_uint(b1.y);
                mma_tf32(acc1[0][ni], af[0], b10, b11);
                mma_tf32(acc1[1][ni], af[1], b10, b11);
                float2 b2 = *reinterpret_cast<const float2*>(
                    sW2 + (ni * 8 + ki) * BF_STRIDE + lane * 2);
                uint32_t b20 = __float_as_uint(b2.x), b21 = __float_as_uint(b2.y);
                mma_tf32(acc2[0][ni], af[0], b20, b21);
                mma_tf32(acc2[1][ni], af[1], b20, b21);
            }
        }
    }

    // ---- epilogue: bias + store both outputs ----
    const size_t obase = ((size_t)mt * 128 + warp * 32) * EE + (size_t)nt * 64;
    float* o1 = out + obase;
    float* o2 = out + (size_t)BB * LL * EE + obase;
    #pragma unroll
    for (int ni = 0; ni < 8; ni++) {
        int col = ni * 8 + 2 * t;
        float ba1 = __ldg(bias1 + nt * 64 + col);
        float bb1 = __ldg(bias1 + nt * 64 + col + 1);
        float ba2 = __ldg(bias2 + nt * 64 + col);
        float bb2 = __ldg(bias2 + nt * 64 + col + 1);
        #pragma unroll
        for (int mi = 0; mi < 2; mi++) {
            size_t roff = (size_t)(mi * 16) * EE;
            *reinterpret_cast<float2*>(o1 + roff + (size_t)g * EE + col) =
                make_float2(acc1[mi][ni][0] + ba1, acc1[mi][ni][1] + bb1);
            *reinterpret_cast<float2*>(o1 + roff + (size_t)(g + 8) * EE + col) =
                make_float2(acc1[mi][ni][2] + ba1, acc1[mi][ni][3] + bb1);
            *reinterpret_cast<float2*>(o2 + roff + (size_t)g * EE + col) =
                make_float2(acc2[mi][ni][0] + ba2, acc2[mi][ni][1] + bb2);
            *reinterpret_cast<float2*>(o2 + roff + (size_t)(g + 8) * EE + col) =
                make_float2(acc2[mi][ni][2] + ba2, acc2[mi][ni][3] + bb2);
        }
    }
}

// ---- launch -----------------------------------------------------------------

extern "C" void kernel_launch(void* const* d_in, const int* in_sizes, int n_in,
                              void* d_out, int out_size) {
    (void)in_sizes; (void)n_in; (void)out_size;
    const float* q  = (const float*)d_in[0];
    const float* k  = (const float*)d_in[1];
    const float* v  = (const float*)d_in[2];
    const float* w1 = (const float*)d_in[3];
    const float* b1 = (const float*)d_in[4];
    const float* w2 = (const float*)d_in[5];
    const float* b2 = (const float*)d_in[6];
    float* out = (float*)d_out;

    cudaFuncSetAttribute((const void*)attn_kernel,
                         cudaFuncAttributeMaxDynamicSharedMemorySize, ATTN_SMEM);
    cudaFuncSetAttribute((const void*)proj_kernel,
                         cudaFuncAttributeMaxDynamicSharedMemorySize, PROJ_SMEM);

    dim3 grid1(LL / QROWS, HH, BB);       // (8, 8, 16) = 1024 blocks
    attn_kernel<<<grid1, 128, ATTN_SMEM>>>(q, k, v);

    dim3 grid2((BB * LL) / 128, EE / 64); // (128, 8) = 1024 blocks
    proj_kernel<<<grid2, 128, PROJ_SMEM>>>(w1, b1, w2, b2, out);
}